// round 15
// baseline (speedup 1.0000x reference)
#include <cuda_runtime.h>
#include <math.h>

#define Bn   8
#define Sn   64
#define Cn   64
#define Hn   32
#define Wn   32
#define NH   8
#define HD   8
#define BS   (Bn*Sn)        // 512
#define TILES (BS*Cn)       // 32768
#define O3   (3*Cn)         // 192
#define En   64

#define NCHUNK 4
#define CH_BS   (BS/NCHUNK)            // 128 bs rows per chunk
#define CH_TILES (CH_BS*Cn)            // 8192 tiles per chunk
#define CH_MODE_BLOCKS (CH_TILES/16)   // 512 mode blocks per chunk

__device__ float g_X[TILES*8];
__device__ float g_Qf[Bn*NH*Sn*56];
__device__ float g_Kf[Bn*NH*Sn*56];
__device__ float g_Vf[Bn*NH*Sn*56];
__device__ float g_bias[NH*Sn*Sn];
__device__ float g_O[Bn*NH*Sn*56];

__device__ __forceinline__ float signlog2(float x) {
    return copysignf(log2f(1.0f + fabsf(x)), x);
}

// ---------------------------------------------------------------------------
// K1: mode extraction (2 tiles/warp, R8-exact). Chunk 0 also carries the 16
// CPB-bias blocks (grid = CH_MODE_BLOCKS+16 for chunk 0 only).
// ---------------------------------------------------------------------------
__global__ void k_modes_bias(const float* __restrict__ x,
                             const float* __restrict__ w1, const float* __restrict__ b1,
                             const float* __restrict__ w2, const int* __restrict__ nsy_p,
                             int tile_base) {
    if (blockIdx.x >= CH_MODE_BLOCKS) {
        int idx = (blockIdx.x - CH_MODE_BLOCKS) * 256 + threadIdx.x;
        int i = idx >> 6, j = idx & 63;
        int ny = *nsy_p;
        float r0 = signlog2((float)(i / ny - j / ny));
        float r1 = signlog2((float)(i % ny - j % ny));
        float outv[NH];
#pragma unroll
        for (int hh = 0; hh < NH; hh++) outv[hh] = 0.f;
        for (int e = 0; e < En; e++) {
            float hv = fmaxf(fmaf(r0, w1[e], fmaf(r1, w1[En + e], b1[e])), 0.f);
#pragma unroll
            for (int hh = 0; hh < NH; hh++) outv[hh] = fmaf(hv, w2[e * NH + hh], outv[hh]);
        }
#pragma unroll
        for (int hh = 0; hh < NH; hh++) g_bias[hh * (Sn * Sn) + idx] = outv[hh];
        return;
    }
    __shared__ float tc[32], ts[32];
    if (threadIdx.x < 32) {
        float s, c;
        sincospif((float)threadIdx.x * (1.0f/16.0f), &s, &c);
        tc[threadIdx.x] = c; ts[threadIdx.x] = s;
    }
    __syncthreads();
    const int warp = threadIdx.x >> 5, lane = threadIdx.x & 31;
    const int tile0 = tile_base + blockIdx.x * 16 + warp * 2;
    const float4* p0 = (const float4*)(x + (size_t)tile0 * 1024) + lane;
    const float4* p1 = p0 + 256;
    const int w0 = (lane & 7) * 4;
    const int h0 = lane >> 3;

    float a0[4] = {0,0,0,0}, bc0[4] = {0,0,0,0}, bs0[4] = {0,0,0,0};
    float a1[4] = {0,0,0,0}, bc1[4] = {0,0,0,0}, bs1[4] = {0,0,0,0};
#pragma unroll
    for (int it = 0; it < 8; it++) {
        float4 v0 = __ldcs(&p0[it * 32]);
        float4 v1 = __ldcs(&p1[it * 32]);
        int hh = h0 + it * 4;
        float c = tc[hh], s = ts[hh];
        a0[0] += v0.x; bc0[0] = fmaf(v0.x, c, bc0[0]); bs0[0] = fmaf(v0.x, s, bs0[0]);
        a0[1] += v0.y; bc0[1] = fmaf(v0.y, c, bc0[1]); bs0[1] = fmaf(v0.y, s, bs0[1]);
        a0[2] += v0.z; bc0[2] = fmaf(v0.z, c, bc0[2]); bs0[2] = fmaf(v0.z, s, bs0[2]);
        a0[3] += v0.w; bc0[3] = fmaf(v0.w, c, bc0[3]); bs0[3] = fmaf(v0.w, s, bs0[3]);
        a1[0] += v1.x; bc1[0] = fmaf(v1.x, c, bc1[0]); bs1[0] = fmaf(v1.x, s, bs1[0]);
        a1[1] += v1.y; bc1[1] = fmaf(v1.y, c, bc1[1]); bs1[1] = fmaf(v1.y, s, bs1[1]);
        a1[2] += v1.z; bc1[2] = fmaf(v1.z, c, bc1[2]); bs1[2] = fmaf(v1.z, s, bs1[2]);
        a1[3] += v1.w; bc1[3] = fmaf(v1.w, c, bc1[3]); bs1[3] = fmaf(v1.w, s, bs1[3]);
    }
    float r0v[7] = {0,0,0,0,0,0,0}, r1v[7] = {0,0,0,0,0,0,0};
#pragma unroll
    for (int j = 0; j < 4; j++) {
        float cw = tc[w0 + j], sw = ts[w0 + j];
        r0v[0] += a0[j];  r0v[1] += bc0[j];  r0v[2] += bs0[j];
        r0v[3] = fmaf(a0[j], cw, r0v[3]);  r0v[4] = fmaf(a0[j], sw, r0v[4]);
        r0v[5] += bc0[j] * cw - bs0[j] * sw;
        r0v[6] += bs0[j] * cw + bc0[j] * sw;
        r1v[0] += a1[j];  r1v[1] += bc1[j];  r1v[2] += bs1[j];
        r1v[3] = fmaf(a1[j], cw, r1v[3]);  r1v[4] = fmaf(a1[j], sw, r1v[4]);
        r1v[5] += bc1[j] * cw - bs1[j] * sw;
        r1v[6] += bs1[j] * cw + bc1[j] * sw;
    }
#pragma unroll
    for (int k = 0; k < 7; k++) {
#pragma unroll
        for (int off = 16; off; off >>= 1) {
            r0v[k] += __shfl_xor_sync(0xffffffffu, r0v[k], off);
            r1v[k] += __shfl_xor_sync(0xffffffffu, r1v[k], off);
        }
    }
    if (lane == 0) {
        float* d0 = g_X + (size_t)tile0 * 8;
        d0[0] = r0v[0]; d0[1] = 0.f;
        d0[2] = r0v[1]; d0[3] = -r0v[2];
        d0[4] = r0v[3]; d0[5] = -r0v[4];
        d0[6] = r0v[5]; d0[7] = -r0v[6];
        float* d1 = d0 + 8;
        d1[0] = r1v[0]; d1[1] = 0.f;
        d1[2] = r1v[1]; d1[3] = -r1v[2];
        d1[4] = r1v[3]; d1[5] = -r1v[4];
        d1[6] = r1v[5]; d1[7] = -r1v[6];
    }
}

// ---------------------------------------------------------------------------
// K2: QKV spectral mixing (R8 exact inner). grid (16,6) per chunk.
// ---------------------------------------------------------------------------
__global__ void k_qkv_mix(const float* __restrict__ wr, const float* __restrict__ wi,
                          int bs_base) {
    __shared__ float Xs[8 * 64 * 8];  // 16KB
    const int bs0 = bs_base + blockIdx.x * 8;
    const int o0  = blockIdx.y * 32;
    const int t = threadIdx.x;
    {
        const float4* gx = (const float4*)(g_X + (size_t)bs0 * 512);
        float4* xs4 = (float4*)Xs;
#pragma unroll
        for (int idx = t; idx < 8 * 64 * 2; idx += 256)
            xs4[idx] = gx[idx];
    }
    __syncthreads();

    const int o_l = t & 31, grp = t >> 5;
    const int o = o0 + o_l;

    float acc[7] = {0,0,0,0,0,0,0};
    const float4* wr4 = (const float4*)wr;
    const float4* wi4 = (const float4*)wi;
#pragma unroll 4
    for (int c = 0; c < 64; c++) {
        float4 w0 = wr4[c * O3 + o];
        float4 w1 = wi4[c * O3 + o];
        float4 x0 = *(const float4*)&Xs[(grp * 64 + c) * 8];
        float4 x1 = *(const float4*)&Xs[(grp * 64 + c) * 8 + 4];
        acc[0] = fmaf(x0.x, w0.x, acc[0]);
        acc[1] = fmaf(x0.z, w0.z, fmaf(-x0.w, w1.z, acc[1]));
        acc[2] = fmaf(x0.z, w1.z, fmaf( x0.w, w0.z, acc[2]));
        acc[3] = fmaf(x1.x, w0.y, fmaf(-x1.y, w1.y, acc[3]));
        acc[4] = fmaf(x1.x, w1.y, fmaf( x1.y, w0.y, acc[4]));
        acc[5] = fmaf(x1.z, w0.w, fmaf(-x1.w, w1.w, acc[5]));
        acc[6] = fmaf(x1.z, w1.w, fmaf( x1.w, w0.w, acc[6]));
    }
    const int which = o >> 6, rem = o & 63;
    const int h = rem >> 3, d = rem & 7;
    const int bs = bs0 + grp;
    const int b = bs >> 6, s = bs & 63;
    size_t base = (((size_t)(b * NH + h) * Sn) + s) * 56 + d * 7;
    if (which == 0) {
        const float cs = 1.0f / (1048576.0f * 2.82842712474619f);
        g_Qf[base + 0] = acc[0] * cs;
        g_Qf[base + 1] = acc[1] * (0.5f * cs);
        g_Qf[base + 2] = acc[2] * (0.5f * cs);
        g_Qf[base + 3] = acc[3] * (2.0f * cs);
        g_Qf[base + 4] = acc[4] * (2.0f * cs);
        g_Qf[base + 5] = acc[5] * (2.0f * cs);
        g_Qf[base + 6] = acc[6] * (2.0f * cs);
    } else {
        float* dst = (which == 1) ? g_Kf : g_Vf;
#pragma unroll
        for (int m = 0; m < 7; m++) dst[base + m] = acc[m];
    }
}

// ---------------------------------------------------------------------------
// K4: attention (R8 exact inner). grid (16,8) per chunk, 128 thr.
// ---------------------------------------------------------------------------
__global__ void k_attn(int bh_base) {
    const int bh = bh_base + blockIdx.x;
    const int h = bh & (NH - 1);
    const int i0 = blockIdx.y * 8;
    __shared__ float Qs[8 * 60];
    __shared__ float Ks[64 * 60];
    __shared__ float Vs[64 * 60];
    __shared__ float Sc[8 * 65];
    const int t = threadIdx.x;

    {
        const float4* kg = (const float4*)(g_Kf + (size_t)bh * 64 * 56);
        const float4* vg = (const float4*)(g_Vf + (size_t)bh * 64 * 56);
        float4* ks4 = (float4*)Ks;
        float4* vs4 = (float4*)Vs;
#pragma unroll
        for (int idx = t; idx < 64 * 14; idx += 128) {
            int row = idx / 14, m = idx - row * 14;
            ks4[row * 15 + m] = kg[idx];
            vs4[row * 15 + m] = vg[idx];
        }
        const float4* qg = (const float4*)(g_Qf + ((size_t)bh * 64 + i0) * 56);
        float4* qs4 = (float4*)Qs;
        if (t < 8 * 14) {
            int row = t / 14, m = t - row * 14;
            qs4[row * 15 + m] = qg[t];
        }
    }
    __syncthreads();

    const int i_l = t >> 4, part = t & 15;
    const int i = i0 + i_l;

    float4 q4[14];
#pragma unroll
    for (int m = 0; m < 14; m++) q4[m] = ((const float4*)Qs)[i_l * 15 + m];

    const float* bias_row = g_bias + h * (Sn * Sn) + i * 64;
    float scv[4];
#pragma unroll
    for (int jj = 0; jj < 4; jj++) {
        int j = jj * 16 + part;
        float a = bias_row[j];
        const float4* kr = (const float4*)Ks + j * 15;
#pragma unroll
        for (int m = 0; m < 14; m++) {
            float4 kv = kr[m];
            a = fmaf(q4[m].x, kv.x, a);
            a = fmaf(q4[m].y, kv.y, a);
            a = fmaf(q4[m].z, kv.z, a);
            a = fmaf(q4[m].w, kv.w, a);
        }
        scv[jj] = a;
    }
    float mx = fmaxf(fmaxf(scv[0], scv[1]), fmaxf(scv[2], scv[3]));
#pragma unroll
    for (int off = 8; off; off >>= 1)
        mx = fmaxf(mx, __shfl_xor_sync(0xffffffffu, mx, off, 16));
    float e0 = __expf(scv[0] - mx), e1 = __expf(scv[1] - mx);
    float e2 = __expf(scv[2] - mx), e3 = __expf(scv[3] - mx);
    float sum = (e0 + e1) + (e2 + e3);
#pragma unroll
    for (int off = 8; off; off >>= 1)
        sum += __shfl_xor_sync(0xffffffffu, sum, off, 16);
    float inv = 1.0f / sum;
    Sc[i_l * 65 +  0 + part] = e0 * inv;
    Sc[i_l * 65 + 16 + part] = e1 * inv;
    Sc[i_l * 65 + 32 + part] = e2 * inv;
    Sc[i_l * 65 + 48 + part] = e3 * inv;
    __syncthreads();

    if (part < 14) {
        const int m0 = part * 4;
        float a0 = 0.f, a1 = 0.f, a2 = 0.f, a3 = 0.f;
        const float* sr = &Sc[i_l * 65];
#pragma unroll 8
        for (int j = 0; j < 64; j++) {
            float a = sr[j];
            float4 vv = *(const float4*)&Vs[j * 60 + m0];
            a0 = fmaf(a, vv.x, a0);
            a1 = fmaf(a, vv.y, a1);
            a2 = fmaf(a, vv.z, a2);
            a3 = fmaf(a, vv.w, a3);
        }
        float* og = g_O + ((size_t)bh * 64 + i) * 56 + m0;
        og[0] = a0; og[1] = a1; og[2] = a2; og[3] = a3;
    }
}

// ---------------------------------------------------------------------------
// K5: output mixing + synthesis (R8 exact inner). grid (128,2) per chunk.
// ---------------------------------------------------------------------------
__global__ void k_out_synth(const float* __restrict__ wr, const float* __restrict__ wi,
                            float* __restrict__ out, int bs_base) {
    __shared__ float Fs[64 * 8];       // 2KB
    __shared__ float Gs[8 * 32 * 8];   // 8KB [grp][o][8]
    __shared__ float tc[32], ts[32];
    const int bs = bs_base + blockIdx.x;
    const int o0 = blockIdx.y * 32;
    const int t = threadIdx.x;

    if (t < 32) {
        float s, c;
        sincospif((float)t * (1.0f/16.0f), &s, &c);
        tc[t] = c; ts[t] = s;
    }
    if (t < 64) Fs[t * 8 + 1] = 0.f;
    for (int idx = t; idx < 64 * 7; idx += 256) {
        int c = idx / 7, m = idx - (idx / 7) * 7;
        int b = bs >> 6, s = bs & 63;
        float v = g_O[(((size_t)(b * NH + (c >> 3)) * Sn) + s) * 56 + (c & 7) * 7 + m];
        int slot = (m == 0) ? 0 : (m + 1);
        float sc = (m == 1 || m == 2) ? 0.5f : 1.0f;
        Fs[c * 8 + slot] = v * sc;
    }
    __syncthreads();

    const int o_l = t & 31, grp = t >> 5;
    const int o = o0 + o_l;
    const int c0 = grp * 8;

    float a0 = 0.f, a1 = 0.f, a2 = 0.f, a3 = 0.f, a4 = 0.f, a5 = 0.f, a6 = 0.f;
    const float4* wr4 = (const float4*)wr;
    const float4* wi4 = (const float4*)wi;
#pragma unroll
    for (int cc = 0; cc < 8; cc++) {
        int c = c0 + cc;
        float4 x0 = *(const float4*)&Fs[c * 8];
        float4 x1 = *(const float4*)&Fs[c * 8 + 4];
        float4 w0 = wr4[c * Cn + o];
        float4 w1 = wi4[c * Cn + o];
        a0 = fmaf(x0.x, w0.x, a0);
        a1 = fmaf(x0.z, w0.z, fmaf(-x0.w, w1.z, a1));
        a2 = fmaf(x0.z, w1.z, fmaf( x0.w, w0.z, a2));
        a3 = fmaf(x1.x, w0.y, fmaf(-x1.y, w1.y, a3));
        a4 = fmaf(x1.x, w1.y, fmaf( x1.y, w0.y, a4));
        a5 = fmaf(x1.z, w0.w, fmaf(-x1.w, w1.w, a5));
        a6 = fmaf(x1.z, w1.w, fmaf( x1.w, w0.w, a6));
    }
    {
        float* g = &Gs[t * 8];
        g[0] = a0; g[1] = 0.f;
        g[2] = a1; g[3] = a2;
        g[4] = a3; g[5] = a4;
        g[6] = a5; g[7] = a6;
    }
    __syncthreads();

    const int warp = t >> 5, lane = t & 31;
    const int w0q = (lane & 7) * 4;
    const int h0 = lane >> 3;
    const float inv = 1.0f / 1024.0f;
#pragma unroll
    for (int k = 0; k < 4; k++) {
        const int tol = warp * 4 + k;
        float g00r = 0.f, g10r = 0.f, g10i = 0.f;
        float g01r = 0.f, g01i = 0.f, g11r = 0.f, g11i = 0.f;
#pragma unroll
        for (int qq = 0; qq < 8; qq++) {
            const float* gp = &Gs[(qq * 32 + tol) * 8];
            g00r += gp[0];
            g10r += gp[2]; g10i += gp[3];
            g01r += gp[4]; g01i += gp[5];
            g11r += gp[6]; g11i += gp[7];
        }
        float P0[4], Pc[4], Ps[4];
#pragma unroll
        for (int jw = 0; jw < 4; jw++) {
            float cw = tc[w0q + jw], sw = ts[w0q + jw];
            P0[jw] = (g00r + 2.0f * (g01r * cw - g01i * sw)) * inv;
            Pc[jw] = (g10r + 2.0f * (g11r * cw - g11i * sw)) * inv;
            Ps[jw] = (-g10i - 2.0f * (g11r * sw + g11i * cw)) * inv;
        }
        float4* dst = (float4*)(out + ((size_t)bs * 64 + o0 + tol) * 1024);
#pragma unroll
        for (int it = 0; it < 8; it++) {
            int hh = h0 + it * 4;
            float c = tc[hh], s = ts[hh];
            float4 v;
            v.x = fmaf(Pc[0], c, fmaf(Ps[0], s, P0[0]));
            v.y = fmaf(Pc[1], c, fmaf(Ps[1], s, P0[1]));
            v.z = fmaf(Pc[2], c, fmaf(Ps[2], s, P0[2]));
            v.w = fmaf(Pc[3], c, fmaf(Ps[3], s, P0[3]));
            __stcs(&dst[hh * 8 + (lane & 7)], v);
        }
    }
}

// ---------------------------------------------------------------------------
// Host: software pipeline. Stream A = read side (modes+qkv), stream B =
// compute/write side (attn+out). Chunk k's write overlaps chunk k+1's read.
// ---------------------------------------------------------------------------
struct PipeRes {
    cudaStream_t sA, sB;
    cudaEvent_t eFork, eQ[NCHUNK], eA, eB;
    PipeRes() {
        cudaStreamCreateWithFlags(&sA, cudaStreamNonBlocking);
        cudaStreamCreateWithFlags(&sB, cudaStreamNonBlocking);
        cudaEventCreateWithFlags(&eFork, cudaEventDisableTiming);
        for (int k = 0; k < NCHUNK; k++)
            cudaEventCreateWithFlags(&eQ[k], cudaEventDisableTiming);
        cudaEventCreateWithFlags(&eA, cudaEventDisableTiming);
        cudaEventCreateWithFlags(&eB, cudaEventDisableTiming);
    }
};

extern "C" void kernel_launch(void* const* d_in, const int* in_sizes, int n_in,
                              void* d_out, int out_size) {
    static PipeRes R;

    const float* seq = (const float*)d_in[0];
    const float* wqr = (const float*)d_in[1];
    const float* wqi = (const float*)d_in[2];
    const float* wor = (const float*)d_in[3];
    const float* woi = (const float*)d_in[4];
    const float* w1  = (const float*)d_in[5];
    const float* b1  = (const float*)d_in[6];
    const float* w2  = (const float*)d_in[7];
    const int* nsy   = (const int*)d_in[9];
    float* out = (float*)d_out;

    cudaEventRecord(R.eFork, 0);
    cudaStreamWaitEvent(R.sA, R.eFork, 0);
    cudaStreamWaitEvent(R.sB, R.eFork, 0);

    // Stream A: read side. Chunk 0 carries the bias blocks.
    for (int k = 0; k < NCHUNK; k++) {
        int extra = (k == 0) ? 16 : 0;
        k_modes_bias<<<CH_MODE_BLOCKS + extra, 256, 0, R.sA>>>(
            seq, w1, b1, w2, nsy, k * CH_TILES);
        k_qkv_mix<<<dim3(CH_BS / 8, 6), 256, 0, R.sA>>>(wqr, wqi, k * CH_BS);
        cudaEventRecord(R.eQ[k], R.sA);
    }
    // Stream B: compute/write side.
    for (int k = 0; k < NCHUNK; k++) {
        cudaStreamWaitEvent(R.sB, R.eQ[k], 0);
        k_attn<<<dim3(CH_BS / 8, 8), 128, 0, R.sB>>>(k * (CH_BS / Sn) * NH);
        k_out_synth<<<dim3(CH_BS, 2), 256, 0, R.sB>>>(wor, woi, out, k * CH_BS);
    }

    cudaEventRecord(R.eA, R.sA);
    cudaEventRecord(R.eB, R.sB);
    cudaStreamWaitEvent(0, R.eA, 0);
    cudaStreamWaitEvent(0, R.eB, 0);
}

// round 16
// speedup vs baseline: 1.4233x; 1.4233x over previous
#include <cuda_runtime.h>
#include <math.h>

#define Bn   8
#define Sn   64
#define Cn   64
#define Hn   32
#define Wn   32
#define NH   8
#define HD   8
#define BS   (Bn*Sn)        // 512
#define TILES (BS*Cn)       // 32768
#define O3   (3*Cn)         // 192
#define En   64

#define MODE_BLOCKS (TILES/16)   // 2048 (2 tiles per warp, 8 warps)

__device__ float g_X[TILES*8];
__device__ float g_Qf[Bn*NH*Sn*56];
__device__ float g_Kf[Bn*NH*Sn*56];
__device__ float g_Vf[Bn*NH*Sn*56];
__device__ float g_bias[NH*Sn*Sn];
__device__ float g_O[Bn*NH*Sn*56];

__device__ __forceinline__ float signlog2(float x) {
    return copysignf(log2f(1.0f + fabsf(x)), x);
}

// ---------------------------------------------------------------------------
// K1: mode extraction (2 tiles/warp, R8-exact) + CPB bias blocks.
// ---------------------------------------------------------------------------
__global__ void k_modes_bias(const float* __restrict__ x,
                             const float* __restrict__ w1, const float* __restrict__ b1,
                             const float* __restrict__ w2, const int* __restrict__ nsy_p) {
    if (blockIdx.x >= MODE_BLOCKS) {
        int idx = (blockIdx.x - MODE_BLOCKS) * 256 + threadIdx.x;
        int i = idx >> 6, j = idx & 63;
        int ny = *nsy_p;
        float r0 = signlog2((float)(i / ny - j / ny));
        float r1 = signlog2((float)(i % ny - j % ny));
        float outv[NH];
#pragma unroll
        for (int hh = 0; hh < NH; hh++) outv[hh] = 0.f;
        for (int e = 0; e < En; e++) {
            float hv = fmaxf(fmaf(r0, w1[e], fmaf(r1, w1[En + e], b1[e])), 0.f);
#pragma unroll
            for (int hh = 0; hh < NH; hh++) outv[hh] = fmaf(hv, w2[e * NH + hh], outv[hh]);
        }
#pragma unroll
        for (int hh = 0; hh < NH; hh++) g_bias[hh * (Sn * Sn) + idx] = outv[hh];
        return;
    }
    __shared__ float tc[32], ts[32];
    if (threadIdx.x < 32) {
        float s, c;
        sincospif((float)threadIdx.x * (1.0f/16.0f), &s, &c);
        tc[threadIdx.x] = c; ts[threadIdx.x] = s;
    }
    __syncthreads();
    const int warp = threadIdx.x >> 5, lane = threadIdx.x & 31;
    const int tile0 = blockIdx.x * 16 + warp * 2;
    const float4* p0 = (const float4*)(x + (size_t)tile0 * 1024) + lane;
    const float4* p1 = p0 + 256;
    const int w0 = (lane & 7) * 4;
    const int h0 = lane >> 3;

    float a0[4] = {0,0,0,0}, bc0[4] = {0,0,0,0}, bs0[4] = {0,0,0,0};
    float a1[4] = {0,0,0,0}, bc1[4] = {0,0,0,0}, bs1[4] = {0,0,0,0};
#pragma unroll
    for (int it = 0; it < 8; it++) {
        float4 v0 = __ldcs(&p0[it * 32]);
        float4 v1 = __ldcs(&p1[it * 32]);
        int hh = h0 + it * 4;
        float c = tc[hh], s = ts[hh];
        a0[0] += v0.x; bc0[0] = fmaf(v0.x, c, bc0[0]); bs0[0] = fmaf(v0.x, s, bs0[0]);
        a0[1] += v0.y; bc0[1] = fmaf(v0.y, c, bc0[1]); bs0[1] = fmaf(v0.y, s, bs0[1]);
        a0[2] += v0.z; bc0[2] = fmaf(v0.z, c, bc0[2]); bs0[2] = fmaf(v0.z, s, bs0[2]);
        a0[3] += v0.w; bc0[3] = fmaf(v0.w, c, bc0[3]); bs0[3] = fmaf(v0.w, s, bs0[3]);
        a1[0] += v1.x; bc1[0] = fmaf(v1.x, c, bc1[0]); bs1[0] = fmaf(v1.x, s, bs1[0]);
        a1[1] += v1.y; bc1[1] = fmaf(v1.y, c, bc1[1]); bs1[1] = fmaf(v1.y, s, bs1[1]);
        a1[2] += v1.z; bc1[2] = fmaf(v1.z, c, bc1[2]); bs1[2] = fmaf(v1.z, s, bs1[2]);
        a1[3] += v1.w; bc1[3] = fmaf(v1.w, c, bc1[3]); bs1[3] = fmaf(v1.w, s, bs1[3]);
    }
    float r0v[7] = {0,0,0,0,0,0,0}, r1v[7] = {0,0,0,0,0,0,0};
#pragma unroll
    for (int j = 0; j < 4; j++) {
        float cw = tc[w0 + j], sw = ts[w0 + j];
        r0v[0] += a0[j];  r0v[1] += bc0[j];  r0v[2] += bs0[j];
        r0v[3] = fmaf(a0[j], cw, r0v[3]);  r0v[4] = fmaf(a0[j], sw, r0v[4]);
        r0v[5] += bc0[j] * cw - bs0[j] * sw;
        r0v[6] += bs0[j] * cw + bc0[j] * sw;
        r1v[0] += a1[j];  r1v[1] += bc1[j];  r1v[2] += bs1[j];
        r1v[3] = fmaf(a1[j], cw, r1v[3]);  r1v[4] = fmaf(a1[j], sw, r1v[4]);
        r1v[5] += bc1[j] * cw - bs1[j] * sw;
        r1v[6] += bs1[j] * cw + bc1[j] * sw;
    }
#pragma unroll
    for (int k = 0; k < 7; k++) {
#pragma unroll
        for (int off = 16; off; off >>= 1) {
            r0v[k] += __shfl_xor_sync(0xffffffffu, r0v[k], off);
            r1v[k] += __shfl_xor_sync(0xffffffffu, r1v[k], off);
        }
    }
    if (lane == 0) {
        float* d0 = g_X + (size_t)tile0 * 8;
        d0[0] = r0v[0]; d0[1] = 0.f;
        d0[2] = r0v[1]; d0[3] = -r0v[2];
        d0[4] = r0v[3]; d0[5] = -r0v[4];
        d0[6] = r0v[5]; d0[7] = -r0v[6];
        float* d1 = d0 + 8;
        d1[0] = r1v[0]; d1[1] = 0.f;
        d1[2] = r1v[1]; d1[3] = -r1v[2];
        d1[4] = r1v[3]; d1[5] = -r1v[4];
        d1[6] = r1v[5]; d1[7] = -r1v[6];
    }
}

// ---------------------------------------------------------------------------
// K2: QKV spectral mixing. Block = 8 bs x 32 o; grid (64,6).
// v2: software-prefetched weight loads + full unroll to maximize LDG MLP
// (R15 profile showed this kernel is L2-latency-chain bound: issue=7%).
// ---------------------------------------------------------------------------
__global__ void k_qkv_mix(const float* __restrict__ wr, const float* __restrict__ wi) {
    __shared__ float Xs[8 * 64 * 8];  // 16KB
    const int bs0 = blockIdx.x * 8;
    const int o0  = blockIdx.y * 32;
    const int t = threadIdx.x;
    {
        const float4* gx = (const float4*)(g_X + (size_t)bs0 * 512);
        float4* xs4 = (float4*)Xs;
#pragma unroll
        for (int idx = t; idx < 8 * 64 * 2; idx += 256)
            xs4[idx] = gx[idx];
    }
    __syncthreads();

    const int o_l = t & 31, grp = t >> 5;
    const int o = o0 + o_l;

    float acc[7] = {0,0,0,0,0,0,0};
    const float4* wr4 = (const float4*)wr + o;
    const float4* wi4 = (const float4*)wi + o;

    // Prefetch 4 c-iterations ahead in a rolling register window.
    float4 w0buf[4], w1buf[4];
#pragma unroll
    for (int k = 0; k < 4; k++) {
        w0buf[k] = __ldg(&wr4[k * O3]);
        w1buf[k] = __ldg(&wi4[k * O3]);
    }
#pragma unroll
    for (int c = 0; c < 64; c++) {
        float4 w0 = w0buf[c & 3];
        float4 w1 = w1buf[c & 3];
        if (c + 4 < 64) {
            w0buf[c & 3] = __ldg(&wr4[(c + 4) * O3]);
            w1buf[c & 3] = __ldg(&wi4[(c + 4) * O3]);
        }
        float4 x0 = *(const float4*)&Xs[(grp * 64 + c) * 8];
        float4 x1 = *(const float4*)&Xs[(grp * 64 + c) * 8 + 4];
        acc[0] = fmaf(x0.x, w0.x, acc[0]);
        acc[1] = fmaf(x0.z, w0.z, fmaf(-x0.w, w1.z, acc[1]));
        acc[2] = fmaf(x0.z, w1.z, fmaf( x0.w, w0.z, acc[2]));
        acc[3] = fmaf(x1.x, w0.y, fmaf(-x1.y, w1.y, acc[3]));
        acc[4] = fmaf(x1.x, w1.y, fmaf( x1.y, w0.y, acc[4]));
        acc[5] = fmaf(x1.z, w0.w, fmaf(-x1.w, w1.w, acc[5]));
        acc[6] = fmaf(x1.z, w1.w, fmaf( x1.w, w0.w, acc[6]));
    }
    const int which = o >> 6, rem = o & 63;
    const int h = rem >> 3, d = rem & 7;
    const int bs = bs0 + grp;
    const int b = bs >> 6, s = bs & 63;
    size_t base = (((size_t)(b * NH + h) * Sn) + s) * 56 + d * 7;
    if (which == 0) {
        const float cs = 1.0f / (1048576.0f * 2.82842712474619f);
        g_Qf[base + 0] = acc[0] * cs;
        g_Qf[base + 1] = acc[1] * (0.5f * cs);
        g_Qf[base + 2] = acc[2] * (0.5f * cs);
        g_Qf[base + 3] = acc[3] * (2.0f * cs);
        g_Qf[base + 4] = acc[4] * (2.0f * cs);
        g_Qf[base + 5] = acc[5] * (2.0f * cs);
        g_Qf[base + 6] = acc[6] * (2.0f * cs);
    } else {
        float* dst = (which == 1) ? g_Kf : g_Vf;
#pragma unroll
        for (int m = 0; m < 7; m++) dst[base + m] = acc[m];
    }
}

// ---------------------------------------------------------------------------
// K4: attention. grid (64 bh, 8 i-chunks of 8), 128 thr. (R8 exact.)
// ---------------------------------------------------------------------------
__global__ void k_attn() {
    const int bh = blockIdx.x;
    const int h = bh & (NH - 1);
    const int i0 = blockIdx.y * 8;
    __shared__ float Qs[8 * 60];
    __shared__ float Ks[64 * 60];
    __shared__ float Vs[64 * 60];
    __shared__ float Sc[8 * 65];
    const int t = threadIdx.x;

    {
        const float4* kg = (const float4*)(g_Kf + (size_t)bh * 64 * 56);
        const float4* vg = (const float4*)(g_Vf + (size_t)bh * 64 * 56);
        float4* ks4 = (float4*)Ks;
        float4* vs4 = (float4*)Vs;
#pragma unroll
        for (int idx = t; idx < 64 * 14; idx += 128) {
            int row = idx / 14, m = idx - row * 14;
            ks4[row * 15 + m] = kg[idx];
            vs4[row * 15 + m] = vg[idx];
        }
        const float4* qg = (const float4*)(g_Qf + ((size_t)bh * 64 + i0) * 56);
        float4* qs4 = (float4*)Qs;
        if (t < 8 * 14) {
            int row = t / 14, m = t - row * 14;
            qs4[row * 15 + m] = qg[t];
        }
    }
    __syncthreads();

    const int i_l = t >> 4, part = t & 15;
    const int i = i0 + i_l;

    float4 q4[14];
#pragma unroll
    for (int m = 0; m < 14; m++) q4[m] = ((const float4*)Qs)[i_l * 15 + m];

    const float* bias_row = g_bias + h * (Sn * Sn) + i * 64;
    float scv[4];
#pragma unroll
    for (int jj = 0; jj < 4; jj++) {
        int j = jj * 16 + part;
        float a = bias_row[j];
        const float4* kr = (const float4*)Ks + j * 15;
#pragma unroll
        for (int m = 0; m < 14; m++) {
            float4 kv = kr[m];
            a = fmaf(q4[m].x, kv.x, a);
            a = fmaf(q4[m].y, kv.y, a);
            a = fmaf(q4[m].z, kv.z, a);
            a = fmaf(q4[m].w, kv.w, a);
        }
        scv[jj] = a;
    }
    float mx = fmaxf(fmaxf(scv[0], scv[1]), fmaxf(scv[2], scv[3]));
#pragma unroll
    for (int off = 8; off; off >>= 1)
        mx = fmaxf(mx, __shfl_xor_sync(0xffffffffu, mx, off, 16));
    float e0 = __expf(scv[0] - mx), e1 = __expf(scv[1] - mx);
    float e2 = __expf(scv[2] - mx), e3 = __expf(scv[3] - mx);
    float sum = (e0 + e1) + (e2 + e3);
#pragma unroll
    for (int off = 8; off; off >>= 1)
        sum += __shfl_xor_sync(0xffffffffu, sum, off, 16);
    float inv = 1.0f / sum;
    Sc[i_l * 65 +  0 + part] = e0 * inv;
    Sc[i_l * 65 + 16 + part] = e1 * inv;
    Sc[i_l * 65 + 32 + part] = e2 * inv;
    Sc[i_l * 65 + 48 + part] = e3 * inv;
    __syncthreads();

    if (part < 14) {
        const int m0 = part * 4;
        float a0 = 0.f, a1 = 0.f, a2 = 0.f, a3 = 0.f;
        const float* sr = &Sc[i_l * 65];
#pragma unroll 8
        for (int j = 0; j < 64; j++) {
            float a = sr[j];
            float4 vv = *(const float4*)&Vs[j * 60 + m0];
            a0 = fmaf(a, vv.x, a0);
            a1 = fmaf(a, vv.y, a1);
            a2 = fmaf(a, vv.z, a2);
            a3 = fmaf(a, vv.w, a3);
        }
        float* og = g_O + ((size_t)bh * 64 + i) * 56 + m0;
        og[0] = a0; og[1] = a1; og[2] = a2; og[3] = a3;
    }
}

// ---------------------------------------------------------------------------
// K5: output mixing + synthesis. grid (512, 2), 256 thr. (R8 exact.)
// ---------------------------------------------------------------------------
__global__ void k_out_synth(const float* __restrict__ wr, const float* __restrict__ wi,
                            float* __restrict__ out) {
    __shared__ float Fs[64 * 8];       // 2KB
    __shared__ float Gs[8 * 32 * 8];   // 8KB [grp][o][8]
    __shared__ float tc[32], ts[32];
    const int bs = blockIdx.x;
    const int o0 = blockIdx.y * 32;
    const int t = threadIdx.x;

    if (t < 32) {
        float s, c;
        sincospif((float)t * (1.0f/16.0f), &s, &c);
        tc[t] = c; ts[t] = s;
    }
    if (t < 64) Fs[t * 8 + 1] = 0.f;
    for (int idx = t; idx < 64 * 7; idx += 256) {
        int c = idx / 7, m = idx - (idx / 7) * 7;
        int b = bs >> 6, s = bs & 63;
        float v = g_O[(((size_t)(b * NH + (c >> 3)) * Sn) + s) * 56 + (c & 7) * 7 + m];
        int slot = (m == 0) ? 0 : (m + 1);
        float sc = (m == 1 || m == 2) ? 0.5f : 1.0f;
        Fs[c * 8 + slot] = v * sc;
    }
    __syncthreads();

    const int o_l = t & 31, grp = t >> 5;
    const int o = o0 + o_l;
    const int c0 = grp * 8;

    float a0 = 0.f, a1 = 0.f, a2 = 0.f, a3 = 0.f, a4 = 0.f, a5 = 0.f, a6 = 0.f;
    const float4* wr4 = (const float4*)wr;
    const float4* wi4 = (const float4*)wi;
#pragma unroll
    for (int cc = 0; cc < 8; cc++) {
        int c = c0 + cc;
        float4 x0 = *(const float4*)&Fs[c * 8];
        float4 x1 = *(const float4*)&Fs[c * 8 + 4];
        float4 w0 = wr4[c * Cn + o];
        float4 w1 = wi4[c * Cn + o];
        a0 = fmaf(x0.x, w0.x, a0);
        a1 = fmaf(x0.z, w0.z, fmaf(-x0.w, w1.z, a1));
        a2 = fmaf(x0.z, w1.z, fmaf( x0.w, w0.z, a2));
        a3 = fmaf(x1.x, w0.y, fmaf(-x1.y, w1.y, a3));
        a4 = fmaf(x1.x, w1.y, fmaf( x1.y, w0.y, a4));
        a5 = fmaf(x1.z, w0.w, fmaf(-x1.w, w1.w, a5));
        a6 = fmaf(x1.z, w1.w, fmaf( x1.w, w0.w, a6));
    }
    {
        float* g = &Gs[t * 8];
        g[0] = a0; g[1] = 0.f;
        g[2] = a1; g[3] = a2;
        g[4] = a3; g[5] = a4;
        g[6] = a5; g[7] = a6;
    }
    __syncthreads();

    const int warp = t >> 5, lane = t & 31;
    const int w0q = (lane & 7) * 4;
    const int h0 = lane >> 3;
    const float inv = 1.0f / 1024.0f;
#pragma unroll
    for (int k = 0; k < 4; k++) {
        const int tol = warp * 4 + k;
        float g00r = 0.f, g10r = 0.f, g10i = 0.f;
        float g01r = 0.f, g01i = 0.f, g11r = 0.f, g11i = 0.f;
#pragma unroll
        for (int qq = 0; qq < 8; qq++) {
            const float* gp = &Gs[(qq * 32 + tol) * 8];
            g00r += gp[0];
            g10r += gp[2]; g10i += gp[3];
            g01r += gp[4]; g01i += gp[5];
            g11r += gp[6]; g11i += gp[7];
        }
        float P0[4], Pc[4], Ps[4];
#pragma unroll
        for (int jw = 0; jw < 4; jw++) {
            float cw = tc[w0q + jw], sw = ts[w0q + jw];
            P0[jw] = (g00r + 2.0f * (g01r * cw - g01i * sw)) * inv;
            Pc[jw] = (g10r + 2.0f * (g11r * cw - g11i * sw)) * inv;
            Ps[jw] = (-g10i - 2.0f * (g11r * sw + g11i * cw)) * inv;
        }
        float4* dst = (float4*)(out + ((size_t)bs * 64 + o0 + tol) * 1024);
#pragma unroll
        for (int it = 0; it < 8; it++) {
            int hh = h0 + it * 4;
            float c = tc[hh], s = ts[hh];
            float4 v;
            v.x = fmaf(Pc[0], c, fmaf(Ps[0], s, P0[0]));
            v.y = fmaf(Pc[1], c, fmaf(Ps[1], s, P0[1]));
            v.z = fmaf(Pc[2], c, fmaf(Ps[2], s, P0[2]));
            v.w = fmaf(Pc[3], c, fmaf(Ps[3], s, P0[3]));
            __stcs(&dst[hh * 8 + (lane & 7)], v);
        }
    }
}

// ---------------------------------------------------------------------------
extern "C" void kernel_launch(void* const* d_in, const int* in_sizes, int n_in,
                              void* d_out, int out_size) {
    const float* seq = (const float*)d_in[0];
    const float* wqr = (const float*)d_in[1];
    const float* wqi = (const float*)d_in[2];
    const float* wor = (const float*)d_in[3];
    const float* woi = (const float*)d_in[4];
    const float* w1  = (const float*)d_in[5];
    const float* b1  = (const float*)d_in[6];
    const float* w2  = (const float*)d_in[7];
    const int* nsy   = (const int*)d_in[9];
    float* out = (float*)d_out;

    k_modes_bias<<<MODE_BLOCKS + 16, 256>>>(seq, w1, b1, w2, nsy);
    k_qkv_mix<<<dim3(64, 6), 256>>>(wqr, wqi);
    k_attn<<<dim3(Bn * NH, 8), 128>>>();
    k_out_synth<<<dim3(512, 2), 256>>>(wor, woi, out);
}

// round 17
// speedup vs baseline: 1.5150x; 1.0645x over previous
#include <cuda_runtime.h>
#include <math.h>

#define Bn   8
#define Sn   64
#define Cn   64
#define Hn   32
#define Wn   32
#define NH   8
#define HD   8
#define BS   (Bn*Sn)        // 512
#define TILES (BS*Cn)       // 32768
#define O3   (3*Cn)         // 192
#define En   64

__device__ float g_Qf[Bn*NH*Sn*56];
__device__ float g_Kf[Bn*NH*Sn*56];
__device__ float g_Vf[Bn*NH*Sn*56];
__device__ float g_bias[NH*Sn*Sn];
__device__ float g_O[Bn*NH*Sn*56];

__device__ __forceinline__ float signlog2(float x) {
    return copysignf(log2f(1.0f + fabsf(x)), x);
}

// ---------------------------------------------------------------------------
// K1: FUSED mode extraction + QKV spectral mixing. One block per bs row.
// Phase 1: 8 warps x 8 channel tiles (2 tiles/round, MLP=16, R8-proven inner),
//          modes go straight to smem (g_X eliminated).
// Phase 2: threads 0..191 compute one qkv output o each: prefetched 64-c loop
//          (R16-proven inner; X reads are smem broadcasts).
// Blocks >= BS are the CPB-bias blocks.
// ---------------------------------------------------------------------------
__global__ void k_modes_qkv(const float* __restrict__ x,
                            const float* __restrict__ wr, const float* __restrict__ wi,
                            const float* __restrict__ w1, const float* __restrict__ b1,
                            const float* __restrict__ w2, const int* __restrict__ nsy_p) {
    if (blockIdx.x >= BS) {
        int idx = (blockIdx.x - BS) * 256 + threadIdx.x;
        int i = idx >> 6, j = idx & 63;
        int ny = *nsy_p;
        float r0 = signlog2((float)(i / ny - j / ny));
        float r1 = signlog2((float)(i % ny - j % ny));
        float outv[NH];
#pragma unroll
        for (int hh = 0; hh < NH; hh++) outv[hh] = 0.f;
        for (int e = 0; e < En; e++) {
            float hv = fmaxf(fmaf(r0, w1[e], fmaf(r1, w1[En + e], b1[e])), 0.f);
#pragma unroll
            for (int hh = 0; hh < NH; hh++) outv[hh] = fmaf(hv, w2[e * NH + hh], outv[hh]);
        }
#pragma unroll
        for (int hh = 0; hh < NH; hh++) g_bias[hh * (Sn * Sn) + idx] = outv[hh];
        return;
    }

    __shared__ float tc[32], ts[32];
    __shared__ float Xs[64 * 8];     // 2KB: modes for this bs row, 64 channels
    const int bs = blockIdx.x;
    const int t = threadIdx.x;
    if (t < 32) {
        float s, c;
        sincospif((float)t * (1.0f/16.0f), &s, &c);
        tc[t] = c; ts[t] = s;
    }
    __syncthreads();

    const int warp = t >> 5, lane = t & 31;
    const int w0 = (lane & 7) * 4;
    const int h0 = lane >> 3;

    // Phase 1: 4 rounds of 2 tiles each -> channels warp*8 .. warp*8+7.
#pragma unroll
    for (int pair = 0; pair < 4; pair++) {
        const int c0 = warp * 8 + pair * 2;
        const float4* p0 = (const float4*)(x + ((size_t)bs * 64 + c0) * 1024) + lane;
        const float4* p1 = p0 + 256;

        float a0[4] = {0,0,0,0}, bc0[4] = {0,0,0,0}, bs0[4] = {0,0,0,0};
        float a1[4] = {0,0,0,0}, bc1[4] = {0,0,0,0}, bs1[4] = {0,0,0,0};
#pragma unroll
        for (int it = 0; it < 8; it++) {
            float4 v0 = __ldcs(&p0[it * 32]);
            float4 v1 = __ldcs(&p1[it * 32]);
            int hh = h0 + it * 4;
            float c = tc[hh], s = ts[hh];
            a0[0] += v0.x; bc0[0] = fmaf(v0.x, c, bc0[0]); bs0[0] = fmaf(v0.x, s, bs0[0]);
            a0[1] += v0.y; bc0[1] = fmaf(v0.y, c, bc0[1]); bs0[1] = fmaf(v0.y, s, bs0[1]);
            a0[2] += v0.z; bc0[2] = fmaf(v0.z, c, bc0[2]); bs0[2] = fmaf(v0.z, s, bs0[2]);
            a0[3] += v0.w; bc0[3] = fmaf(v0.w, c, bc0[3]); bs0[3] = fmaf(v0.w, s, bs0[3]);
            a1[0] += v1.x; bc1[0] = fmaf(v1.x, c, bc1[0]); bs1[0] = fmaf(v1.x, s, bs1[0]);
            a1[1] += v1.y; bc1[1] = fmaf(v1.y, c, bc1[1]); bs1[1] = fmaf(v1.y, s, bs1[1]);
            a1[2] += v1.z; bc1[2] = fmaf(v1.z, c, bc1[2]); bs1[2] = fmaf(v1.z, s, bs1[2]);
            a1[3] += v1.w; bc1[3] = fmaf(v1.w, c, bc1[3]); bs1[3] = fmaf(v1.w, s, bs1[3]);
        }
        float r0v[7] = {0,0,0,0,0,0,0}, r1v[7] = {0,0,0,0,0,0,0};
#pragma unroll
        for (int j = 0; j < 4; j++) {
            float cw = tc[w0 + j], sw = ts[w0 + j];
            r0v[0] += a0[j];  r0v[1] += bc0[j];  r0v[2] += bs0[j];
            r0v[3] = fmaf(a0[j], cw, r0v[3]);  r0v[4] = fmaf(a0[j], sw, r0v[4]);
            r0v[5] += bc0[j] * cw - bs0[j] * sw;
            r0v[6] += bs0[j] * cw + bc0[j] * sw;
            r1v[0] += a1[j];  r1v[1] += bc1[j];  r1v[2] += bs1[j];
            r1v[3] = fmaf(a1[j], cw, r1v[3]);  r1v[4] = fmaf(a1[j], sw, r1v[4]);
            r1v[5] += bc1[j] * cw - bs1[j] * sw;
            r1v[6] += bs1[j] * cw + bc1[j] * sw;
        }
#pragma unroll
        for (int k = 0; k < 7; k++) {
#pragma unroll
            for (int off = 16; off; off >>= 1) {
                r0v[k] += __shfl_xor_sync(0xffffffffu, r0v[k], off);
                r1v[k] += __shfl_xor_sync(0xffffffffu, r1v[k], off);
            }
        }
        if (lane == 0) {
            float* d0 = &Xs[c0 * 8];
            d0[0] = r0v[0]; d0[1] = 0.f;
            d0[2] = r0v[1]; d0[3] = -r0v[2];
            d0[4] = r0v[3]; d0[5] = -r0v[4];
            d0[6] = r0v[5]; d0[7] = -r0v[6];
            float* d1 = d0 + 8;
            d1[0] = r1v[0]; d1[1] = 0.f;
            d1[2] = r1v[1]; d1[3] = -r1v[2];
            d1[4] = r1v[3]; d1[5] = -r1v[4];
            d1[6] = r1v[5]; d1[7] = -r1v[6];
        }
    }
    __syncthreads();

    // Phase 2: QKV mix, one output o per thread (t < 192), prefetched weights.
    if (t >= O3) return;
    const int o = t;

    float acc[7] = {0,0,0,0,0,0,0};
    const float4* wr4 = (const float4*)wr + o;
    const float4* wi4 = (const float4*)wi + o;

    float4 w0buf[4], w1buf[4];
#pragma unroll
    for (int k = 0; k < 4; k++) {
        w0buf[k] = __ldg(&wr4[k * O3]);
        w1buf[k] = __ldg(&wi4[k * O3]);
    }
#pragma unroll
    for (int c = 0; c < 64; c++) {
        float4 w0v = w0buf[c & 3];
        float4 w1v = w1buf[c & 3];
        if (c + 4 < 64) {
            w0buf[c & 3] = __ldg(&wr4[(c + 4) * O3]);
            w1buf[c & 3] = __ldg(&wi4[(c + 4) * O3]);
        }
        float4 x0 = *(const float4*)&Xs[c * 8];
        float4 x1 = *(const float4*)&Xs[c * 8 + 4];
        acc[0] = fmaf(x0.x, w0v.x, acc[0]);
        acc[1] = fmaf(x0.z, w0v.z, fmaf(-x0.w, w1v.z, acc[1]));
        acc[2] = fmaf(x0.z, w1v.z, fmaf( x0.w, w0v.z, acc[2]));
        acc[3] = fmaf(x1.x, w0v.y, fmaf(-x1.y, w1v.y, acc[3]));
        acc[4] = fmaf(x1.x, w1v.y, fmaf( x1.y, w0v.y, acc[4]));
        acc[5] = fmaf(x1.z, w0v.w, fmaf(-x1.w, w1v.w, acc[5]));
        acc[6] = fmaf(x1.z, w1v.w, fmaf( x1.w, w0v.w, acc[6]));
    }
    const int which = o >> 6, rem = o & 63;
    const int h = rem >> 3, d = rem & 7;
    const int b = bs >> 6, s = bs & 63;
    size_t base = (((size_t)(b * NH + h) * Sn) + s) * 56 + d * 7;
    if (which == 0) {
        const float cs = 1.0f / (1048576.0f * 2.82842712474619f);
        g_Qf[base + 0] = acc[0] * cs;
        g_Qf[base + 1] = acc[1] * (0.5f * cs);
        g_Qf[base + 2] = acc[2] * (0.5f * cs);
        g_Qf[base + 3] = acc[3] * (2.0f * cs);
        g_Qf[base + 4] = acc[4] * (2.0f * cs);
        g_Qf[base + 5] = acc[5] * (2.0f * cs);
        g_Qf[base + 6] = acc[6] * (2.0f * cs);
    } else {
        float* dst = (which == 1) ? g_Kf : g_Vf;
#pragma unroll
        for (int m = 0; m < 7; m++) dst[base + m] = acc[m];
    }
}

// ---------------------------------------------------------------------------
// K4: attention. grid (64 bh, 8 i-chunks of 8), 128 thr. (R8 exact.)
// ---------------------------------------------------------------------------
__global__ void k_attn() {
    const int bh = blockIdx.x;
    const int h = bh & (NH - 1);
    const int i0 = blockIdx.y * 8;
    __shared__ float Qs[8 * 60];
    __shared__ float Ks[64 * 60];
    __shared__ float Vs[64 * 60];
    __shared__ float Sc[8 * 65];
    const int t = threadIdx.x;

    {
        const float4* kg = (const float4*)(g_Kf + (size_t)bh * 64 * 56);
        const float4* vg = (const float4*)(g_Vf + (size_t)bh * 64 * 56);
        float4* ks4 = (float4*)Ks;
        float4* vs4 = (float4*)Vs;
#pragma unroll
        for (int idx = t; idx < 64 * 14; idx += 128) {
            int row = idx / 14, m = idx - row * 14;
            ks4[row * 15 + m] = kg[idx];
            vs4[row * 15 + m] = vg[idx];
        }
        const float4* qg = (const float4*)(g_Qf + ((size_t)bh * 64 + i0) * 56);
        float4* qs4 = (float4*)Qs;
        if (t < 8 * 14) {
            int row = t / 14, m = t - row * 14;
            qs4[row * 15 + m] = qg[t];
        }
    }
    __syncthreads();

    const int i_l = t >> 4, part = t & 15;
    const int i = i0 + i_l;

    float4 q4[14];
#pragma unroll
    for (int m = 0; m < 14; m++) q4[m] = ((const float4*)Qs)[i_l * 15 + m];

    const float* bias_row = g_bias + h * (Sn * Sn) + i * 64;
    float scv[4];
#pragma unroll
    for (int jj = 0; jj < 4; jj++) {
        int j = jj * 16 + part;
        float a = bias_row[j];
        const float4* kr = (const float4*)Ks + j * 15;
#pragma unroll
        for (int m = 0; m < 14; m++) {
            float4 kv = kr[m];
            a = fmaf(q4[m].x, kv.x, a);
            a = fmaf(q4[m].y, kv.y, a);
            a = fmaf(q4[m].z, kv.z, a);
            a = fmaf(q4[m].w, kv.w, a);
        }
        scv[jj] = a;
    }
    float mx = fmaxf(fmaxf(scv[0], scv[1]), fmaxf(scv[2], scv[3]));
#pragma unroll
    for (int off = 8; off; off >>= 1)
        mx = fmaxf(mx, __shfl_xor_sync(0xffffffffu, mx, off, 16));
    float e0 = __expf(scv[0] - mx), e1 = __expf(scv[1] - mx);
    float e2 = __expf(scv[2] - mx), e3 = __expf(scv[3] - mx);
    float sum = (e0 + e1) + (e2 + e3);
#pragma unroll
    for (int off = 8; off; off >>= 1)
        sum += __shfl_xor_sync(0xffffffffu, sum, off, 16);
    float inv = 1.0f / sum;
    Sc[i_l * 65 +  0 + part] = e0 * inv;
    Sc[i_l * 65 + 16 + part] = e1 * inv;
    Sc[i_l * 65 + 32 + part] = e2 * inv;
    Sc[i_l * 65 + 48 + part] = e3 * inv;
    __syncthreads();

    if (part < 14) {
        const int m0 = part * 4;
        float a0 = 0.f, a1 = 0.f, a2 = 0.f, a3 = 0.f;
        const float* sr = &Sc[i_l * 65];
#pragma unroll 8
        for (int j = 0; j < 64; j++) {
            float a = sr[j];
            float4 vv = *(const float4*)&Vs[j * 60 + m0];
            a0 = fmaf(a, vv.x, a0);
            a1 = fmaf(a, vv.y, a1);
            a2 = fmaf(a, vv.z, a2);
            a3 = fmaf(a, vv.w, a3);
        }
        float* og = g_O + ((size_t)bh * 64 + i) * 56 + m0;
        og[0] = a0; og[1] = a1; og[2] = a2; og[3] = a3;
    }
}

// ---------------------------------------------------------------------------
// K5: output mixing + synthesis. grid (512, 2), 256 thr. (R8 exact.)
// ---------------------------------------------------------------------------
__global__ void k_out_synth(const float* __restrict__ wr, const float* __restrict__ wi,
                            float* __restrict__ out) {
    __shared__ float Fs[64 * 8];       // 2KB
    __shared__ float Gs[8 * 32 * 8];   // 8KB [grp][o][8]
    __shared__ float tc[32], ts[32];
    const int bs = blockIdx.x;
    const int o0 = blockIdx.y * 32;
    const int t = threadIdx.x;

    if (t < 32) {
        float s, c;
        sincospif((float)t * (1.0f/16.0f), &s, &c);
        tc[t] = c; ts[t] = s;
    }
    if (t < 64) Fs[t * 8 + 1] = 0.f;
    for (int idx = t; idx < 64 * 7; idx += 256) {
        int c = idx / 7, m = idx - (idx / 7) * 7;
        int b = bs >> 6, s = bs & 63;
        float v = g_O[(((size_t)(b * NH + (c >> 3)) * Sn) + s) * 56 + (c & 7) * 7 + m];
        int slot = (m == 0) ? 0 : (m + 1);
        float sc = (m == 1 || m == 2) ? 0.5f : 1.0f;
        Fs[c * 8 + slot] = v * sc;
    }
    __syncthreads();

    const int o_l = t & 31, grp = t >> 5;
    const int o = o0 + o_l;
    const int c0 = grp * 8;

    float a0 = 0.f, a1 = 0.f, a2 = 0.f, a3 = 0.f, a4 = 0.f, a5 = 0.f, a6 = 0.f;
    const float4* wr4 = (const float4*)wr;
    const float4* wi4 = (const float4*)wi;
#pragma unroll
    for (int cc = 0; cc < 8; cc++) {
        int c = c0 + cc;
        float4 x0 = *(const float4*)&Fs[c * 8];
        float4 x1 = *(const float4*)&Fs[c * 8 + 4];
        float4 w0 = wr4[c * Cn + o];
        float4 w1 = wi4[c * Cn + o];
        a0 = fmaf(x0.x, w0.x, a0);
        a1 = fmaf(x0.z, w0.z, fmaf(-x0.w, w1.z, a1));
        a2 = fmaf(x0.z, w1.z, fmaf( x0.w, w0.z, a2));
        a3 = fmaf(x1.x, w0.y, fmaf(-x1.y, w1.y, a3));
        a4 = fmaf(x1.x, w1.y, fmaf( x1.y, w0.y, a4));
        a5 = fmaf(x1.z, w0.w, fmaf(-x1.w, w1.w, a5));
        a6 = fmaf(x1.z, w1.w, fmaf( x1.w, w0.w, a6));
    }
    {
        float* g = &Gs[t * 8];
        g[0] = a0; g[1] = 0.f;
        g[2] = a1; g[3] = a2;
        g[4] = a3; g[5] = a4;
        g[6] = a5; g[7] = a6;
    }
    __syncthreads();

    const int warp = t >> 5, lane = t & 31;
    const int w0q = (lane & 7) * 4;
    const int h0 = lane >> 3;
    const float inv = 1.0f / 1024.0f;
#pragma unroll
    for (int k = 0; k < 4; k++) {
        const int tol = warp * 4 + k;
        float g00r = 0.f, g10r = 0.f, g10i = 0.f;
        float g01r = 0.f, g01i = 0.f, g11r = 0.f, g11i = 0.f;
#pragma unroll
        for (int qq = 0; qq < 8; qq++) {
            const float* gp = &Gs[(qq * 32 + tol) * 8];
            g00r += gp[0];
            g10r += gp[2]; g10i += gp[3];
            g01r += gp[4]; g01i += gp[5];
            g11r += gp[6]; g11i += gp[7];
        }
        float P0[4], Pc[4], Ps[4];
#pragma unroll
        for (int jw = 0; jw < 4; jw++) {
            float cw = tc[w0q + jw], sw = ts[w0q + jw];
            P0[jw] = (g00r + 2.0f * (g01r * cw - g01i * sw)) * inv;
            Pc[jw] = (g10r + 2.0f * (g11r * cw - g11i * sw)) * inv;
            Ps[jw] = (-g10i - 2.0f * (g11r * sw + g11i * cw)) * inv;
        }
        float4* dst = (float4*)(out + ((size_t)bs * 64 + o0 + tol) * 1024);
#pragma unroll
        for (int it = 0; it < 8; it++) {
            int hh = h0 + it * 4;
            float c = tc[hh], s = ts[hh];
            float4 v;
            v.x = fmaf(Pc[0], c, fmaf(Ps[0], s, P0[0]));
            v.y = fmaf(Pc[1], c, fmaf(Ps[1], s, P0[1]));
            v.z = fmaf(Pc[2], c, fmaf(Ps[2], s, P0[2]));
            v.w = fmaf(Pc[3], c, fmaf(Ps[3], s, P0[3]));
            __stcs(&dst[hh * 8 + (lane & 7)], v);
        }
    }
}

// ---------------------------------------------------------------------------
extern "C" void kernel_launch(void* const* d_in, const int* in_sizes, int n_in,
                              void* d_out, int out_size) {
    const float* seq = (const float*)d_in[0];
    const float* wqr = (const float*)d_in[1];
    const float* wqi = (const float*)d_in[2];
    const float* wor = (const float*)d_in[3];
    const float* woi = (const float*)d_in[4];
    const float* w1  = (const float*)d_in[5];
    const float* b1  = (const float*)d_in[6];
    const float* w2  = (const float*)d_in[7];
    const int* nsy   = (const int*)d_in[9];
    float* out = (float*)d_out;

    k_modes_qkv<<<BS + 16, 256>>>(seq, wqr, wqi, w1, b1, w2, nsy);
    k_attn<<<dim3(Bn * NH, 8), 128>>>();
    k_out_synth<<<dim3(512, 2), 256>>>(wor, woi, out);
}